// round 5
// baseline (speedup 1.0000x reference)
#include <cuda_runtime.h>
#include <cuda_fp16.h>
#include <cstdint>

#define F    128
#define E    16
#define KN   32
#define Q    (E * F)   // 2048
#define MT   16        // nodes per CTA
#define NT   256
#define SSTR 24        // halves per S row (48B stride: 16B-aligned, 4-way store conflicts max)

#define S_BYTES     (Q * SSTR * 2)                 // 98304
#define EB_OFF_B    S_BYTES                        // edges staging (fp32): 2 x 32 x 16
#define EB_BYTES    (2 * KN * E * 4)               // 4096
#define IB_OFF_B    (EB_OFF_B + EB_BYTES)
#define SMEM_BYTES  (IB_OFF_B + 2 * KN * 4)        // 102656 B -> 2 CTAs/SM

// Pre-transposed weights: W2[q*128 + m] = w[l*2048 + m*16 + n], q = n*128 + l.
__device__ float g_W2[Q * F];
__device__ int g_is64;

// ---------- packed f32x2 helpers ----------
__device__ __forceinline__ void ffma2(unsigned long long& d,
                                      unsigned long long a,
                                      unsigned long long b) {
    asm("fma.rn.f32x2 %0, %1, %2, %0;" : "+l"(d) : "l"(a), "l"(b));
}
__device__ __forceinline__ unsigned long long pk2(float x, float y) {
    unsigned long long r;
    asm("mov.b64 %0, {%1, %2};" : "=l"(r) : "f"(x), "f"(y));
    return r;
}
__device__ __forceinline__ void unpk2(float& x, float& y, unsigned long long v) {
    asm("mov.b64 {%0, %1}, %2;" : "=f"(x), "=f"(y) : "l"(v));
}
__device__ __forceinline__ unsigned long long h2_to_pk2(unsigned int h2) {
    float2 f = __half22float2(*(const __half2*)&h2);
    return pk2(f.x, f.y);
}

// ---------- kernel 1: setup = transpose w -> g_W2, plus nlist dtype detect ----------
__global__ void setup_kernel(const float* __restrict__ w,
                             const int* __restrict__ nl) {
    if (blockIdx.x == 0 && threadIdx.x < 32) {
        int odd_nonzero = (threadIdx.x < 16) ? (nl[2 * threadIdx.x + 1] != 0) : 0;
        unsigned any = __ballot_sync(0xffffffffu, odd_nonzero);
        if (threadIdx.x == 0) g_is64 = (any == 0u) ? 1 : 0;
    }
    int o = blockIdx.x * blockDim.x + threadIdx.x;
    if (o >= Q * F) return;
    int m = o & (F - 1);
    int q = o >> 7;
    int l = q & (F - 1);
    int n = q >> 7;
    g_W2[o] = w[((l << 7) + m) * E + n];
}

// ---------- kernel 2: fused gather + contraction ----------
__global__ void __launch_bounds__(NT, 2)
mp_kernel(const float* __restrict__ nodes,
          const void* __restrict__ nlist_raw,
          const float* __restrict__ edges,
          float* __restrict__ out,
          int N) {
    extern __shared__ char smem[];
    __half* S  = (__half*)smem;                    // [Q][SSTR]
    float*  eb = (float*)(smem + EB_OFF_B);        // [2][KN*E]
    int*    ib = (int*)(smem + IB_OFF_B);          // [2][KN]

    const int tid  = threadIdx.x;
    const int base = blockIdx.x * MT;
    const int is64 = g_is64;

    const long long* nl64 = (const long long*)nlist_raw;
    const int*       nl32 = (const int*)nlist_raw;

    // ===== Stage 1: S[q][v] = sum_j nodes[idx[v][j], l] * edges[base+v, j, n] =====
    {
        const int l   = tid & (F - 1);
        const int sub = tid >> 7;       // 0/1
        for (int it = 0; it < MT / 2; ++it) {
            const int v = it * 2 + sub;
            const int i = base + v;
            const bool valid = (i < N);

            __syncthreads();   // protect previous iteration's eb/ib

            if (valid) {
                ((float4*)(eb + sub * (KN * E)))[l] =
                    ((const float4*)(edges + (size_t)i * (KN * E)))[l];
                if (l < KN) {
                    int nb = is64 ? (int)nl64[(size_t)i * KN + l]
                                  :      nl32[(size_t)i * KN + l];
                    ib[sub * KN + l] = nb;
                }
            }
            __syncthreads();

            if (valid) {
                unsigned long long acc[E / 2];
                #pragma unroll
                for (int p = 0; p < E / 2; ++p) acc[p] = 0ull;

                const float* ebs = eb + sub * (KN * E);
                const int*   ibs = ib + sub * KN;

                #pragma unroll
                for (int j0 = 0; j0 < KN; j0 += 8) {
                    float x[8];
                    #pragma unroll
                    for (int u = 0; u < 8; ++u) {
                        int nb = ibs[j0 + u];
                        x[u] = nodes[(size_t)nb * F + l];   // coalesced over l
                    }
                    #pragma unroll
                    for (int u = 0; u < 8; ++u) {
                        unsigned long long xx = pk2(x[u], x[u]);
                        const unsigned long long* ep =
                            (const unsigned long long*)(ebs + (j0 + u) * E);
                        #pragma unroll
                        for (int p = 0; p < E / 2; ++p)
                            ffma2(acc[p], xx, ep[p]);
                    }
                }

                #pragma unroll
                for (int p = 0; p < E / 2; ++p) {
                    float a, b;
                    unpk2(a, b, acc[p]);
                    S[((2 * p)     * F + l) * SSTR + v] = __float2half_rn(a);
                    S[((2 * p + 1) * F + l) * SSTR + v] = __float2half_rn(b);
                }
            }
        }
        __syncthreads();
    }

    // ===== Stage 2: register-tiled GEMM: out[v][m] = (1/K) sum_q S[q][v] * W2[q][m] =====
    // thread = (mg = tid&63 -> m = 2mg, 2mg+1; qs = tid>>6 -> q in [qs*512, qs*512+512)).
    // Per q: 1 LDG.64 (W, 2 m) + 2 broadcast LDS.128 (16 nodes, fp16) + 8 cvt -> 16 FFMA2.
    const int mg = tid & 63;
    const int qs = tid >> 6;
    const float2* W2f2 = ((const float2*)g_W2) + mg;    // + q*64
    const char*   Sb   = (const char*)S;

    unsigned long long acc[2][8];   // [m'][node-pair]
    #pragma unroll
    for (int mp = 0; mp < 2; ++mp)
        #pragma unroll
        for (int p = 0; p < 8; ++p) acc[mp][p] = 0ull;

    const int qbase = qs << 9;
    #pragma unroll 1
    for (int q0 = 0; q0 < 512; q0 += 8) {
        float2 wv[8];
        #pragma unroll
        for (int u = 0; u < 8; ++u)
            wv[u] = W2f2[(size_t)((qbase + q0 + u) << 6)];   // 8 coalesced LDG.64 in flight
        #pragma unroll
        for (int u = 0; u < 8; ++u) {
            const char* row = Sb + (size_t)(qbase + q0 + u) * (SSTR * 2);
            const uint4 ra = *(const uint4*)(row);        // nodes 0..7  (fp16)
            const uint4 rb = *(const uint4*)(row + 16);   // nodes 8..15
            unsigned long long s[8];
            s[0] = h2_to_pk2(ra.x);  s[1] = h2_to_pk2(ra.y);
            s[2] = h2_to_pk2(ra.z);  s[3] = h2_to_pk2(ra.w);
            s[4] = h2_to_pk2(rb.x);  s[5] = h2_to_pk2(rb.y);
            s[6] = h2_to_pk2(rb.z);  s[7] = h2_to_pk2(rb.w);
            const unsigned long long wp0 = pk2(wv[u].x, wv[u].x);
            const unsigned long long wp1 = pk2(wv[u].y, wv[u].y);
            #pragma unroll
            for (int p = 0; p < 8; ++p) ffma2(acc[0][p], s[p], wp0);
            #pragma unroll
            for (int p = 0; p < 8; ++p) ffma2(acc[1][p], s[p], wp1);
        }
    }

    // ===== Cross-qs reduction through smem (S region is dead now) =====
    __syncthreads();
    unsigned long long* red = (unsigned long long*)smem;  // [(mp*8+p)][qs*66 + mg], row stride 264
    #pragma unroll
    for (int mp = 0; mp < 2; ++mp)
        #pragma unroll
        for (int p = 0; p < 8; ++p)
            red[(mp * 8 + p) * 264 + qs * 66 + mg] = acc[mp][p];
    __syncthreads();

    const float inv_k = 1.0f / (float)KN;
    #pragma unroll
    for (int oi = 0; oi < 4; ++oi) {
        const int id = oi * 256 + tid;       // 0..1023
        const int m  = id & 127;             // lanes consecutive m -> coalesced STG
        const int p  = id >> 7;              // node-pair 0..7
        const int mgr = m >> 1;
        const int mpr = m & 1;
        float a = 0.f, b = 0.f;
        #pragma unroll
        for (int q2 = 0; q2 < 4; ++q2) {
            float x, y;
            unpk2(x, y, red[(mpr * 8 + p) * 264 + q2 * 66 + mgr]);
            a += x; b += y;
        }
        const int i0 = base + 2 * p;
        if (i0 < N)     out[(size_t)i0 * F + m]       = a * inv_k;
        if (i0 + 1 < N) out[(size_t)(i0 + 1) * F + m] = b * inv_k;
    }
}

// ---------- launch ----------
extern "C" void kernel_launch(void* const* d_in, const int* in_sizes, int n_in,
                              void* d_out, int out_size) {
    // Identify inputs by element count:
    //   w = F*F*E = 262144, edges = largest, nodes = edges/4, nlist = edges/16.
    int iw = -1, ie = -1, ino = -1, inl = -1;
    long long emax = -1;
    for (int t = 0; t < n_in; ++t)
        if (in_sizes[t] == F * F * E) iw = t;
    for (int t = 0; t < n_in; ++t)
        if (t != iw && (long long)in_sizes[t] > emax) { emax = in_sizes[t]; ie = t; }
    for (int t = 0; t < n_in; ++t) {
        if (t == iw || t == ie) continue;
        if ((long long)in_sizes[t] * 4 == emax)  ino = t;
        if ((long long)in_sizes[t] * 16 == emax) inl = t;
    }
    if (iw < 0 || ie < 0 || ino < 0 || inl < 0) { ino = 0; inl = 1; ie = 2; iw = 3; }

    const float* nodes = (const float*)d_in[ino];
    const void*  nlist = d_in[inl];
    const float* edges = (const float*)d_in[ie];
    const float* w     = (const float*)d_in[iw];
    float*       out   = (float*)d_out;

    const int N = in_sizes[ino] / F;

    setup_kernel<<<(Q * F + NT - 1) / NT, NT>>>(w, (const int*)nlist);

    cudaFuncSetAttribute(mp_kernel,
                         cudaFuncAttributeMaxDynamicSharedMemorySize,
                         SMEM_BYTES);
    const int blocks = (N + MT - 1) / MT;
    mp_kernel<<<blocks, NT, SMEM_BYTES>>>(nodes, nlist, edges, out, N);
}

// round 6
// speedup vs baseline: 1.3327x; 1.3327x over previous
#include <cuda_runtime.h>
#include <cstdint>

#define F    128
#define E    16
#define KN   32
#define Q    (E * F)   // 2048
#define MT   12        // nodes per CTA (48B fp32 S rows -> 2 CTAs/SM)
#define NT   256

#define S_FLOATS    (Q * MT)                       // 24576 floats = 98304 B
#define EB_OFF      S_FLOATS
#define EB_FLOATS   (2 * KN * E)                   // 1024
#define IB_OFF_B    ((EB_OFF + EB_FLOATS) * 4)
#define SMEM_BYTES  (IB_OFF_B + 2 * KN * 4)        // 102656 B -> 2 CTAs/SM

// Pre-transposed weights: W2[q*128 + m] = w[l*2048 + m*16 + n], q = n*128 + l.
__device__ float g_W2[Q * F];
__device__ int g_is64;

// ---------- packed f32x2 helpers ----------
__device__ __forceinline__ void ffma2(unsigned long long& d,
                                      unsigned long long a,
                                      unsigned long long b) {
    asm("fma.rn.f32x2 %0, %1, %2, %0;" : "+l"(d) : "l"(a), "l"(b));
}
__device__ __forceinline__ unsigned long long pk2(float x, float y) {
    unsigned long long r;
    asm("mov.b64 %0, {%1, %2};" : "=l"(r) : "f"(x), "f"(y));
    return r;
}
__device__ __forceinline__ void unpk2(float& x, float& y, unsigned long long v) {
    asm("mov.b64 {%0, %1}, %2;" : "=f"(x), "=f"(y) : "l"(v));
}

// ---------- kernel 1: setup = transpose w -> g_W2, plus nlist dtype detect ----------
__global__ void setup_kernel(const float* __restrict__ w,
                             const int* __restrict__ nl) {
    if (blockIdx.x == 0 && threadIdx.x < 32) {
        int odd_nonzero = (threadIdx.x < 16) ? (nl[2 * threadIdx.x + 1] != 0) : 0;
        unsigned any = __ballot_sync(0xffffffffu, odd_nonzero);
        if (threadIdx.x == 0) g_is64 = (any == 0u) ? 1 : 0;
    }
    int o = blockIdx.x * blockDim.x + threadIdx.x;
    if (o >= Q * F) return;
    int m = o & (F - 1);
    int q = o >> 7;
    int l = q & (F - 1);
    int n = q >> 7;
    g_W2[o] = w[((l << 7) + m) * E + n];
}

// ---------- kernel 2: fused gather + contraction ----------
__global__ void __launch_bounds__(NT, 2)
mp_kernel(const float* __restrict__ nodes,
          const void* __restrict__ nlist_raw,
          const float* __restrict__ edges,
          float* __restrict__ out,
          int N) {
    extern __shared__ float smem[];
    float* S  = smem;                              // [Q][MT] fp32
    float* eb = smem + EB_OFF;                     // [2][KN*E]
    int*   ib = (int*)((char*)smem + IB_OFF_B);    // [2][KN]

    const int tid  = threadIdx.x;
    const int base = blockIdx.x * MT;
    const int is64 = g_is64;

    const long long* nl64 = (const long long*)nlist_raw;
    const int*       nl32 = (const int*)nlist_raw;

    // ===== Stage 1: S[q][v] = sum_j nodes[idx[v][j], l] * edges[base+v, j, n] =====
    {
        const int l   = tid & (F - 1);
        const int sub = tid >> 7;       // 0/1
        for (int it = 0; it < MT / 2; ++it) {
            const int v = it * 2 + sub;
            const int i = base + v;
            const bool valid = (i < N);

            __syncthreads();   // protect previous iteration's eb/ib

            if (valid) {
                ((float4*)(eb + sub * (KN * E)))[l] =
                    ((const float4*)(edges + (size_t)i * (KN * E)))[l];
                if (l < KN) {
                    int nb = is64 ? (int)nl64[(size_t)i * KN + l]
                                  :      nl32[(size_t)i * KN + l];
                    ib[sub * KN + l] = nb;
                }
            }
            __syncthreads();

            if (valid) {
                unsigned long long acc[E / 2];
                #pragma unroll
                for (int p = 0; p < E / 2; ++p) acc[p] = 0ull;

                const float* ebs = eb + sub * (KN * E);
                const int*   ibs = ib + sub * KN;

                #pragma unroll
                for (int j0 = 0; j0 < KN; j0 += 8) {
                    float x[8];
                    #pragma unroll
                    for (int u = 0; u < 8; ++u) {
                        int nb = ibs[j0 + u];
                        x[u] = nodes[(size_t)nb * F + l];   // coalesced over l
                    }
                    #pragma unroll
                    for (int u = 0; u < 8; ++u) {
                        unsigned long long xx = pk2(x[u], x[u]);
                        const unsigned long long* ep =
                            (const unsigned long long*)(ebs + (j0 + u) * E);
                        #pragma unroll
                        for (int p = 0; p < E / 2; ++p)
                            ffma2(acc[p], xx, ep[p]);
                    }
                }

                #pragma unroll
                for (int p = 0; p < E / 2; ++p) {
                    float a, b;
                    unpk2(a, b, acc[p]);
                    S[((2 * p)     * F + l) * MT + v] = a;
                    S[((2 * p + 1) * F + l) * MT + v] = b;
                }
            }
        }
        __syncthreads();
    }

    // ===== Stage 2: register-tiled GEMM: out[v][m] = (1/K) sum_q S[q][v] * W2[q][m] =====
    // thread = (mg = tid&31 -> m = 4mg..4mg+3; qs = tid>>5 -> q in [qs*256, qs*256+256)).
    // Per q: 1 LDG.128 (W, 4 m) + 3 broadcast LDS.128 (12 nodes) + 4 pk2 -> 24 FFMA2.
    const int mg = tid & 31;
    const int qs = tid >> 5;
    const float4* W4 = ((const float4*)g_W2) + mg;   // + q*32
    const float*  Sh = S + (qs << 8) * MT;

    unsigned long long acc[4][6];   // [m'][node-pair]
    #pragma unroll
    for (int mp = 0; mp < 4; ++mp)
        #pragma unroll
        for (int p = 0; p < 6; ++p) acc[mp][p] = 0ull;

    #pragma unroll 1
    for (int q0 = 0; q0 < 256; q0 += 8) {
        float4 wv[8];
        #pragma unroll
        for (int u = 0; u < 8; ++u)
            wv[u] = W4[(size_t)(((qs << 8) + q0 + u) << 5)];   // 8 coalesced LDG.128 in flight
        #pragma unroll
        for (int u = 0; u < 8; ++u) {
            const float* row = Sh + (q0 + u) * MT;
            const ulonglong2 sA = *(const ulonglong2*)(row);       // nodes 0..3
            const ulonglong2 sB = *(const ulonglong2*)(row + 4);   // nodes 4..7
            const ulonglong2 sC = *(const ulonglong2*)(row + 8);   // nodes 8..11
            const unsigned long long s[6] = {sA.x, sA.y, sB.x, sB.y, sC.x, sC.y};
            unsigned long long wp[4];
            wp[0] = pk2(wv[u].x, wv[u].x);
            wp[1] = pk2(wv[u].y, wv[u].y);
            wp[2] = pk2(wv[u].z, wv[u].z);
            wp[3] = pk2(wv[u].w, wv[u].w);
            #pragma unroll
            for (int mp = 0; mp < 4; ++mp)
                #pragma unroll
                for (int p = 0; p < 6; ++p)
                    ffma2(acc[mp][p], s[p], wp[mp]);
        }
    }

    // ===== Cross-qs reduction through smem (S region is dead now) =====
    __syncthreads();
    unsigned long long* red = (unsigned long long*)smem;  // [(mp*6+p)*265 + qs*33 + mg]
    #pragma unroll
    for (int mp = 0; mp < 4; ++mp)
        #pragma unroll
        for (int p = 0; p < 6; ++p)
            red[(mp * 6 + p) * 265 + qs * 33 + mg] = acc[mp][p];
    __syncthreads();

    const float inv_k = 1.0f / (float)KN;
    #pragma unroll
    for (int oi = 0; oi < 3; ++oi) {
        const int id = oi * 256 + tid;       // 0..767 = (node-pair p, m)
        const int m  = id & 127;             // consecutive m -> coalesced STG
        const int p  = id >> 7;              // node-pair 0..5
        const int mgr = m >> 2;
        const int mpr = m & 3;
        float a = 0.f, b = 0.f;
        #pragma unroll
        for (int q2 = 0; q2 < 8; ++q2) {
            float x, y;
            unpk2(x, y, red[(mpr * 6 + p) * 265 + q2 * 33 + mgr]);
            a += x; b += y;
        }
        const int i0 = base + 2 * p;
        if (i0 < N)     out[(size_t)i0 * F + m]       = a * inv_k;
        if (i0 + 1 < N) out[(size_t)(i0 + 1) * F + m] = b * inv_k;
    }
}

// ---------- launch ----------
extern "C" void kernel_launch(void* const* d_in, const int* in_sizes, int n_in,
                              void* d_out, int out_size) {
    // Identify inputs by element count:
    //   w = F*F*E = 262144, edges = largest, nodes = edges/4, nlist = edges/16.
    int iw = -1, ie = -1, ino = -1, inl = -1;
    long long emax = -1;
    for (int t = 0; t < n_in; ++t)
        if (in_sizes[t] == F * F * E) iw = t;
    for (int t = 0; t < n_in; ++t)
        if (t != iw && (long long)in_sizes[t] > emax) { emax = in_sizes[t]; ie = t; }
    for (int t = 0; t < n_in; ++t) {
        if (t == iw || t == ie) continue;
        if ((long long)in_sizes[t] * 4 == emax)  ino = t;
        if ((long long)in_sizes[t] * 16 == emax) inl = t;
    }
    if (iw < 0 || ie < 0 || ino < 0 || inl < 0) { ino = 0; inl = 1; ie = 2; iw = 3; }

    const float* nodes = (const float*)d_in[ino];
    const void*  nlist = d_in[inl];
    const float* edges = (const float*)d_in[ie];
    const float* w     = (const float*)d_in[iw];
    float*       out   = (float*)d_out;

    const int N = in_sizes[ino] / F;

    setup_kernel<<<(Q * F + NT - 1) / NT, NT>>>(w, (const int*)nlist);

    cudaFuncSetAttribute(mp_kernel,
                         cudaFuncAttributeMaxDynamicSharedMemorySize,
                         SMEM_BYTES);
    const int blocks = (N + MT - 1) / MT;
    mp_kernel<<<blocks, NT, SMEM_BYTES>>>(nodes, nlist, edges, out, N);
}